// round 10
// baseline (speedup 1.0000x reference)
#include <cuda_runtime.h>
#include <cuda_bf16.h>

#define NQ      65536
#define PP      2048
#define NT      32                 // tiles per side (256/8)
#define NTILES  1024
#define NREG    256                // 16x16 regions of 16px
#define CAPQ    256                // queries per tile bucket (mean 64)
#define CAPT    192                // kept nodes per tile (mean ~40-70)
#define CAPC    384                // region candidates (mean ~100-170)
#define LOG2E   1.4426950408889634f
#define THRESH  26.0f              // log2 cut: dropped mass <= 2048*2^-26 ~ 3e-5

// Static device state (zero-initialized at module load; no allocation).
__device__ int      g_ncnt[NTILES];
__device__ float    g_list[(size_t)NTILES * CAPT * 8];   // 6 MB records
__device__ int      g_qcnt[NTILES];                      // reset by k_main
__device__ int      g_fin[NTILES];                       // per-tile done count
__device__ unsigned g_qdat[NTILES * CAPQ];               // packed q<<16|y<<8|x

__device__ __forceinline__ float ex2f(float x) {
    float r; asm("ex2.approx.f32 %0,%1;" : "=f"(r) : "f"(x)); return r;
}

// ---------------------------------------------------------------------------
// K1: one CTA per 16x16px region (256 CTAs x 256 thr).  [unchanged, proven]
//  - scatter 256 queries
//  - level A: filter 2048 nodes -> ~130 region candidates (smem)
//  - level B: per 8px sub-tile (4), 2 warps each: tile bound + keep + records
// ---------------------------------------------------------------------------
__global__ __launch_bounds__(256)
void k_prep(const int2* __restrict__ X,
            const int2* __restrict__ pat,
            const float* __restrict__ W2,
            const float* __restrict__ sig) {
    __shared__ float4 cand[CAPC];        // {px, py, C, bitcast(p)}
    __shared__ float  wred[8];
    __shared__ int    wcnt[8];
    __shared__ float  sbB[4][2];
    __shared__ int    scB[4][2];
    __shared__ int    s_nc;

    const int tid  = threadIdx.x;
    const int lane = tid & 31;
    const int wrp  = tid >> 5;
    const int r    = blockIdx.x;
    const int rx   = r >> 4, ry = r & 15;
    const float X0 = (float)(rx << 4), X1 = X0 + 15.0f;
    const float Y0 = (float)(ry << 4), Y1 = Y0 + 15.0f;

    // -- Query scatter: this CTA owns queries [256r, 256r+256) --
    {
        int i = (r << 8) + tid;
        int2 xy = X[i];
        int tt = (xy.x >> 3) * NT + (xy.y >> 3);
        int pos = atomicAdd(&g_qcnt[tt], 1);
        if (pos < CAPQ)
            g_qdat[tt * CAPQ + pos] =
                ((unsigned)i << 16) | ((unsigned)xy.y << 8) | (unsigned)xy.x;
    }

    // -- Level A: 8 nodes/thread, region bound + keep metric --
    float4 v[8];
    float keepm[8];
    float bestA = -1e30f;
#pragma unroll
    for (int k = 0; k < 8; k++) {
        int p = (k << 8) + tid;                        // coalesced
        int2 pp = pat[p];
        float px = (float)pp.x, py = (float)pp.y;
        float C = __fdividef(-0.5f * LOG2E, sig[p]);   // negative (MUFU rcp)
        float dxm = fmaxf(fabsf(px - X0), fabsf(px - X1));
        float dym = fmaxf(fabsf(py - Y0), fabsf(py - Y1));
        bestA = fmaxf(bestA, C * fmaf(dxm, dxm, dym * dym));
        float dxc = fmaxf(fmaxf(X0 - px, px - X1), 0.0f);
        float dyc = fmaxf(fmaxf(Y0 - py, py - Y1), 0.0f);
        keepm[k] = C * fmaf(dxc, dxc, dyc * dyc);
        v[k] = make_float4(px, py, C, __int_as_float(p));
    }
    for (int o = 16; o; o >>= 1)
        bestA = fmaxf(bestA, __shfl_xor_sync(0xffffffffu, bestA, o));
    if (lane == 0) wred[wrp] = bestA;
    __syncthreads();
    float cutA;
    {
        float b = wred[0];
#pragma unroll
        for (int w = 1; w < 8; w++) b = fmaxf(b, wred[w]);
        cutA = b - THRESH;
    }

    // warp-major ballot compaction of candidates (fixed order)
    int mycnt = 0;
    unsigned masks[8];
#pragma unroll
    for (int k = 0; k < 8; k++) {
        masks[k] = __ballot_sync(0xffffffffu, keepm[k] >= cutA);
        mycnt += __popc(masks[k]);
    }
    if (lane == 0) wcnt[wrp] = mycnt;
    __syncthreads();
    int base = 0, total = 0;
#pragma unroll
    for (int w = 0; w < 8; w++) {
        if (w < wrp) base += wcnt[w];
        total += wcnt[w];
    }
    if (tid == 0) s_nc = total < CAPC ? total : CAPC;
#pragma unroll
    for (int k = 0; k < 8; k++) {
        unsigned m = masks[k];
        if ((m >> lane) & 1u) {
            int rk = base + __popc(m & ((1u << lane) - 1u));
            if (rk < CAPC) cand[rk] = v[k];
        }
        base += __popc(m);
    }
    __syncthreads();
    const int nc = s_nc;

    // -- Level B: warp -> (sub-tile st = wrp>>1, half = wrp&1) --
    const int st   = wrp >> 1;
    const int half = wrp & 1;
    const int stx  = 2 * rx + (st >> 1);
    const int sty  = 2 * ry + (st & 1);
    const float bx0 = (float)(stx << 3), bx1 = bx0 + 7.0f;
    const float by0 = (float)(sty << 3), by1 = by0 + 7.0f;

    const int R  = (nc + 31) >> 5;
    const int Rh = (R + 1) >> 1;
    const int r0 = half ? Rh : 0;
    const int r1 = half ? R : Rh;

    // pass 1: tile max bound over candidates
    float bb = -1e30f;
    for (int rr = r0; rr < r1; rr++) {
        int j = (rr << 5) + lane;
        if (j < nc) {
            float4 c = cand[j];
            float dxm = fmaxf(fabsf(c.x - bx0), fabsf(c.x - bx1));
            float dym = fmaxf(fabsf(c.y - by0), fabsf(c.y - by1));
            bb = fmaxf(bb, c.z * fmaf(dxm, dxm, dym * dym));
        }
    }
    for (int o = 16; o; o >>= 1)
        bb = fmaxf(bb, __shfl_xor_sync(0xffffffffu, bb, o));
    if (lane == 0) sbB[st][half] = bb;
    __syncthreads();
    const float cutB = fmaxf(sbB[st][0], sbB[st][1]) - THRESH;

    // pass 2: keep counts
    int kc = 0;
    for (int rr = r0; rr < r1; rr++) {
        int j = (rr << 5) + lane;
        bool keep = false;
        if (j < nc) {
            float4 c = cand[j];
            float dxc = fmaxf(fmaxf(bx0 - c.x, c.x - bx1), 0.0f);
            float dyc = fmaxf(fmaxf(by0 - c.y, c.y - by1), 0.0f);
            keep = (c.z * fmaf(dxc, dxc, dyc * dyc) >= cutB);
        }
        kc += __popc(__ballot_sync(0xffffffffu, keep));
    }
    if (lane == 0) scB[st][half] = kc;
    __syncthreads();

    const int t = stx * NT + sty;
    int wbase = half ? scB[st][0] : 0;
    // pass 3: write records (order: half0 keeps then half1 keeps; fixed)
    float4* dst = (float4*)(g_list + (size_t)t * CAPT * 8);
    for (int rr = r0; rr < r1; rr++) {
        int j = (rr << 5) + lane;
        bool keep = false;
        float4 c = make_float4(0.f, 0.f, 0.f, 0.f);
        if (j < nc) {
            c = cand[j];
            float dxc = fmaxf(fmaxf(bx0 - c.x, c.x - bx1), 0.0f);
            float dyc = fmaxf(fmaxf(by0 - c.y, c.y - by1), 0.0f);
            keep = (c.z * fmaf(dxc, dxc, dyc * dyc) >= cutB);
        }
        unsigned m = __ballot_sync(0xffffffffu, keep);
        if (keep) {
            int rk = wbase + __popc(m & ((1u << lane) - 1u));
            if (rk < CAPT) {
                int p = __float_as_int(c.w);
                float C = c.z;
                dst[2 * rk + 0] = make_float4(-2.0f * C * c.x, -2.0f * C * c.y,
                                              C * fmaf(c.x, c.x, c.y * c.y), C);
                dst[2 * rk + 1] = make_float4(W2[p], W2[PP + p],
                                              W2[2 * PP + p], 0.0f);
            }
        }
        wbase += __popc(m);
    }
    if (lane == 0 && half == 0) {
        int nkT = scB[st][0] + scB[st][1];
        g_ncnt[t] = nkT < CAPT ? nkT : CAPT;
    }
}

// ---------------------------------------------------------------------------
// K2: per-tile evaluation, 2 CTAs per tile (halved query range -> single
// pass, 2x SM overlap). 128 threads = 64 query-slots x 2 node-chunks,
// smem reduce. Fixed orders => bitwise-deterministic.
// Reset protocol: last-finished CTA of each tile zeroes g_qcnt/g_fin.
// ---------------------------------------------------------------------------
__global__ __launch_bounds__(128)
void k_main(float* __restrict__ out) {
    __shared__ float4 sh[2 * CAPT];          // 6 KB records
    __shared__ float4 red[128];
    const int tid = threadIdx.x;
    const int t = blockIdx.x >> 1;
    const int s = blockIdx.x & 1;
    const int nn = g_ncnt[t];
    const int cnt = min(g_qcnt[t], CAPQ);
    const int h  = (cnt + 1) >> 1;           // split point
    const int q0 = s ? h : 0;
    const int q1 = s ? cnt : h;

    const float4* lst = (const float4*)(g_list + (size_t)t * CAPT * 8);
    for (int i = tid; i < 2 * nn; i += 128)
        sh[i] = lst[i];
    __syncthreads();

    const int chunk = tid >> 6;              // 0 or 1
    const int qslot = tid & 63;
    for (int qb = q0; qb < q1; qb += 64) {   // one iteration in practice
        int qi = qb + qslot;
        float4 acc = make_float4(0.f, 0.f, 0.f, 0.f);
        if (qi < q1) {
            unsigned d = g_qdat[t * CAPQ + qi];
            float x0 = (float)(d & 255u);
            float x1 = (float)((d >> 8) & 255u);
            float xx = fmaf(x0, x0, x1 * x1);
#pragma unroll 4
            for (int j = chunk; j < nn; j += 2) {
                float4 a = sh[2 * j];
                float4 b = sh[2 * j + 1];
                float arg = fmaf(a.w, xx, a.z);
                arg = fmaf(a.x, x0, arg);
                arg = fmaf(a.y, x1, arg);
                float e = ex2f(arg);
                acc.x += e;
                acc.y = fmaf(e, b.x, acc.y);
                acc.z = fmaf(e, b.y, acc.z);
                acc.w = fmaf(e, b.z, acc.w);
            }
        }
        red[tid] = acc;
        __syncthreads();
        if (tid < 64 && qb + tid < q1) {
            float4 a0 = red[tid];
            float4 a1 = red[64 + tid];
            float den = a0.x + a1.x;
            float inv = 1.0f / den;
            int q = (int)(g_qdat[t * CAPQ + qb + tid] >> 16);
            out[3 * q + 0] = (a0.y + a1.y) * inv;
            out[3 * q + 1] = (a0.z + a1.z) * inv;
            out[3 * q + 2] = (a0.w + a1.w) * inv;
        }
        __syncthreads();
    }

    // Last CTA of this tile resets state for the next graph replay.
    if (tid == 0) {
        __threadfence();
        int old = atomicAdd(&g_fin[t], 1);
        if (old == 1) {                      // both halves done
            g_qcnt[t] = 0;
            g_fin[t] = 0;
            __threadfence();
        }
    }
}

// ---------------------------------------------------------------------------
extern "C" void kernel_launch(void* const* d_in, const int* in_sizes, int n_in,
                              void* d_out, int out_size) {
    const int*   X   = (const int*)d_in[0];     // [N,2] int32
    const int*   pat = (const int*)d_in[1];     // [P,2] int32
    const float* W2  = (const float*)d_in[2];   // [C,P] f32
    const float* sig = (const float*)d_in[3];   // [P]   f32
    float* out = (float*)d_out;
    (void)in_sizes; (void)n_in; (void)out_size;

    k_prep<<<NREG, 256>>>((const int2*)X, (const int2*)pat, W2, sig);
    k_main<<<NTILES * 2, 128>>>(out);
}

// round 11
// speedup vs baseline: 1.6250x; 1.6250x over previous
#include <cuda_runtime.h>
#include <cuda_bf16.h>

#define NQ      65536
#define PP      2048
#define NREG    256                // 16x16 regions of 16px
#define CAPC    384                // region candidates (mean ~136, >20 sigma)
#define LOG2E   1.4426950408889634f
#define THRESH  26.0f              // log2 cut: dropped mass <= 2048*2^-26 ~ 3e-5

// Pixel table: out0,out1,out2,den per pixel (1 MB, stateless, rewritten fully
// each replay -> no reset protocol, deterministic).
__device__ float4 g_tab[256 * 256];

__device__ __forceinline__ float ex2f(float x) {
    float r; asm("ex2.approx.f32 %0,%1;" : "=f"(r) : "f"(x)); return r;
}

// ---------------------------------------------------------------------------
// K1: one CTA per 16x16px region. Level-A cull (2048 -> ~130 candidates,
// deterministic ascending compaction), record build, then each thread
// evaluates ONE fixed pixel of the region. No atomics, no buckets.
// ---------------------------------------------------------------------------
__global__ __launch_bounds__(256)
void k_eval(const int2* __restrict__ pat,
            const float* __restrict__ W2,
            const float* __restrict__ sig) {
    __shared__ float4 cand[CAPC];        // {px, py, C, bitcast(p)}
    __shared__ float4 recA[CAPC];        // {A0, A1, B, C}
    __shared__ float4 recB[CAPC];        // {W0, W1, W2, 0}
    __shared__ float  wred[8];
    __shared__ int    wcnt[8];
    __shared__ int    s_nc;

    const int tid  = threadIdx.x;
    const int lane = tid & 31;
    const int wrp  = tid >> 5;
    const int r    = blockIdx.x;
    const int rx   = r >> 4, ry = r & 15;
    const float X0 = (float)(rx << 4), X1 = X0 + 15.0f;
    const float Y0 = (float)(ry << 4), Y1 = Y0 + 15.0f;

    // -- Level A: 8 nodes/thread, region max bound + keep metric --
    float4 v[8];
    float keepm[8];
    float bestA = -1e30f;
#pragma unroll
    for (int k = 0; k < 8; k++) {
        int p = (k << 8) + tid;                        // coalesced
        int2 pp = pat[p];
        float px = (float)pp.x, py = (float)pp.y;
        float C = __fdividef(-0.5f * LOG2E, sig[p]);   // negative (MUFU rcp)
        float dxm = fmaxf(fabsf(px - X0), fabsf(px - X1));
        float dym = fmaxf(fabsf(py - Y0), fabsf(py - Y1));
        bestA = fmaxf(bestA, C * fmaf(dxm, dxm, dym * dym));
        float dxc = fmaxf(fmaxf(X0 - px, px - X1), 0.0f);
        float dyc = fmaxf(fmaxf(Y0 - py, py - Y1), 0.0f);
        keepm[k] = C * fmaf(dxc, dxc, dyc * dyc);
        v[k] = make_float4(px, py, C, __int_as_float(p));
    }
    for (int o = 16; o; o >>= 1)
        bestA = fmaxf(bestA, __shfl_xor_sync(0xffffffffu, bestA, o));
    if (lane == 0) wred[wrp] = bestA;
    __syncthreads();
    float cutA;
    {
        float b = wred[0];
#pragma unroll
        for (int w = 1; w < 8; w++) b = fmaxf(b, wred[w]);
        cutA = b - THRESH;
    }

    // -- Ballot compaction (warp-major, fixed ascending order) --
    int mycnt = 0;
    unsigned masks[8];
#pragma unroll
    for (int k = 0; k < 8; k++) {
        masks[k] = __ballot_sync(0xffffffffu, keepm[k] >= cutA);
        mycnt += __popc(masks[k]);
    }
    if (lane == 0) wcnt[wrp] = mycnt;
    __syncthreads();
    int base = 0, total = 0;
#pragma unroll
    for (int w = 0; w < 8; w++) {
        if (w < wrp) base += wcnt[w];
        total += wcnt[w];
    }
    if (tid == 0) s_nc = total < CAPC ? total : CAPC;
#pragma unroll
    for (int k = 0; k < 8; k++) {
        unsigned m = masks[k];
        if ((m >> lane) & 1u) {
            int rk = base + __popc(m & ((1u << lane) - 1u));
            if (rk < CAPC) cand[rk] = v[k];
        }
        base += __popc(m);
    }
    __syncthreads();
    const int nc = s_nc;

    // -- Build eval records (parallel, one pass) --
    for (int i = tid; i < nc; i += 256) {
        float4 c = cand[i];
        int p = __float_as_int(c.w);
        float C = c.z;
        recA[i] = make_float4(-2.0f * C * c.x, -2.0f * C * c.y,
                              C * fmaf(c.x, c.x, c.y * c.y), C);
        recB[i] = make_float4(W2[p], W2[PP + p], W2[2 * PP + p], 0.0f);
    }
    __syncthreads();

    // -- Eval: thread -> pixel (x = rx*16 + tid/16, y = ry*16 + tid%16) --
    const int ix = (rx << 4) + (tid >> 4);
    const int iy = (ry << 4) + (tid & 15);
    const float x0 = (float)ix, x1 = (float)iy;
    const float xx = fmaf(x0, x0, x1 * x1);

    float den = 0.f, n0 = 0.f, n1 = 0.f, n2 = 0.f;
#pragma unroll 4
    for (int j = 0; j < nc; j++) {
        float4 a = recA[j];                  // broadcast LDS
        float4 b = recB[j];
        float arg = fmaf(a.w, xx, a.z);
        arg = fmaf(a.x, x0, arg);
        arg = fmaf(a.y, x1, arg);
        float e = ex2f(arg);
        den += e;
        n0 = fmaf(e, b.x, n0);
        n1 = fmaf(e, b.y, n1);
        n2 = fmaf(e, b.z, n2);
    }
    float inv = 1.0f / den;
    g_tab[(ix << 8) + iy] = make_float4(n0 * inv, n1 * inv, n2 * inv, den);
}

// ---------------------------------------------------------------------------
// K2: gather — out[n] = tab[X[n]]. Coalesced X read, random L2-hit LDG.128.
// ---------------------------------------------------------------------------
__global__ __launch_bounds__(256)
void k_gather(const int2* __restrict__ X, float* __restrict__ out) {
    int i = blockIdx.x * 256 + threadIdx.x;
    int2 xy = X[i];
    float4 v = g_tab[(xy.x << 8) + xy.y];
    out[3 * i + 0] = v.x;
    out[3 * i + 1] = v.y;
    out[3 * i + 2] = v.z;
}

// ---------------------------------------------------------------------------
extern "C" void kernel_launch(void* const* d_in, const int* in_sizes, int n_in,
                              void* d_out, int out_size) {
    const int*   X   = (const int*)d_in[0];     // [N,2] int32
    const int*   pat = (const int*)d_in[1];     // [P,2] int32
    const float* W2  = (const float*)d_in[2];   // [C,P] f32
    const float* sig = (const float*)d_in[3];   // [P]   f32
    float* out = (float*)d_out;
    (void)in_sizes; (void)n_in; (void)out_size;

    k_eval<<<NREG, 256>>>((const int2*)pat, W2, sig);
    k_gather<<<NQ / 256, 256>>>((const int2*)X, out);
}

// round 12
// speedup vs baseline: 1.6617x; 1.0226x over previous
#include <cuda_runtime.h>
#include <cuda_bf16.h>

#define NQ      65536
#define PP      2048
#define NREG    256                // 16x16 regions of 16px
#define CAPC    384                // region candidates (mean ~136, >20 sigma)
#define LOG2E   1.4426950408889634f
#define THRESH  26.0f              // log2 cut: dropped mass <= 2048*2^-26 ~ 3e-5

// Static device state. g_tab fully rewritten each replay; barrier counters
// reset by the last-finishing CTA -> deterministic across graph replays.
__device__ float4   g_tab[256 * 256];        // 1 MB pixel table
__device__ unsigned g_arrive;
__device__ unsigned g_done;

__device__ __forceinline__ float ex2f(float x) {
    float r; asm("ex2.approx.f32 %0,%1;" : "=f"(r) : "f"(x)); return r;
}

// ---------------------------------------------------------------------------
// Single fused kernel. 256 CTAs x 256 thr, occ>=2 => all CTAs co-resident,
// so the software grid barrier is deadlock-free.
//   Phase 0: prefetch this CTA's 256 queries (independent of eval)
//   Phase 1: region cull (2048 -> ~130 cands) + per-pixel RBF eval -> g_tab
//   Barrier
//   Phase 2: out[q] = g_tab[pixel(q)] for queries [256r, 256r+256)
// ---------------------------------------------------------------------------
__global__ __launch_bounds__(256, 2)
void k_all(const int2* __restrict__ X,
           const int2* __restrict__ pat,
           const float* __restrict__ W2,
           const float* __restrict__ sig,
           float* __restrict__ out) {
    __shared__ float4 cand[CAPC];        // {px, py, C, bitcast(p)}
    __shared__ float4 recA[CAPC];        // {A0, A1, B, C}
    __shared__ float4 recB[CAPC];        // {W0, W1, W2, 0}
    __shared__ float  wred[8];
    __shared__ int    wcnt[8];
    __shared__ int    s_nc;

    const int tid  = threadIdx.x;
    const int lane = tid & 31;
    const int wrp  = tid >> 5;
    const int r    = blockIdx.x;
    const int rx   = r >> 4, ry = r & 15;
    const float X0 = (float)(rx << 4), X1 = X0 + 15.0f;
    const float Y0 = (float)(ry << 4), Y1 = Y0 + 15.0f;

    // -- Phase 0: prefetch this CTA's query (coalesced, held in regs) --
    const int qidx = (r << 8) + tid;
    const int2 qxy = X[qidx];

    // -- Phase 1a: level-A cull. 8 nodes/thread, bound + keep metric --
    float4 v[8];
    float keepm[8];
    float bestA = -1e30f;
#pragma unroll
    for (int k = 0; k < 8; k++) {
        int p = (k << 8) + tid;                        // coalesced
        int2 pp = pat[p];
        float px = (float)pp.x, py = (float)pp.y;
        float C = __fdividef(-0.5f * LOG2E, sig[p]);   // negative (MUFU rcp)
        float dxm = fmaxf(fabsf(px - X0), fabsf(px - X1));
        float dym = fmaxf(fabsf(py - Y0), fabsf(py - Y1));
        bestA = fmaxf(bestA, C * fmaf(dxm, dxm, dym * dym));
        float dxc = fmaxf(fmaxf(X0 - px, px - X1), 0.0f);
        float dyc = fmaxf(fmaxf(Y0 - py, py - Y1), 0.0f);
        keepm[k] = C * fmaf(dxc, dxc, dyc * dyc);
        v[k] = make_float4(px, py, C, __int_as_float(p));
    }
    for (int o = 16; o; o >>= 1)
        bestA = fmaxf(bestA, __shfl_xor_sync(0xffffffffu, bestA, o));
    if (lane == 0) wred[wrp] = bestA;
    __syncthreads();
    float cutA;
    {
        float b = wred[0];
#pragma unroll
        for (int w = 1; w < 8; w++) b = fmaxf(b, wred[w]);
        cutA = b - THRESH;
    }

    // -- Ballot compaction (warp-major, fixed ascending order) --
    int mycnt = 0;
    unsigned masks[8];
#pragma unroll
    for (int k = 0; k < 8; k++) {
        masks[k] = __ballot_sync(0xffffffffu, keepm[k] >= cutA);
        mycnt += __popc(masks[k]);
    }
    if (lane == 0) wcnt[wrp] = mycnt;
    __syncthreads();
    int base = 0, total = 0;
#pragma unroll
    for (int w = 0; w < 8; w++) {
        if (w < wrp) base += wcnt[w];
        total += wcnt[w];
    }
    if (tid == 0) s_nc = total < CAPC ? total : CAPC;
#pragma unroll
    for (int k = 0; k < 8; k++) {
        unsigned m = masks[k];
        if ((m >> lane) & 1u) {
            int rk = base + __popc(m & ((1u << lane) - 1u));
            if (rk < CAPC) cand[rk] = v[k];
        }
        base += __popc(m);
    }
    __syncthreads();
    const int nc = s_nc;

    // -- Phase 1b: build eval records (parallel) --
    for (int i = tid; i < nc; i += 256) {
        float4 c = cand[i];
        int p = __float_as_int(c.w);
        float C = c.z;
        recA[i] = make_float4(-2.0f * C * c.x, -2.0f * C * c.y,
                              C * fmaf(c.x, c.x, c.y * c.y), C);
        recB[i] = make_float4(W2[p], W2[PP + p], W2[2 * PP + p], 0.0f);
    }
    __syncthreads();

    // -- Phase 1c: eval this thread's pixel --
    const int ix = (rx << 4) + (tid >> 4);
    const int iy = (ry << 4) + (tid & 15);
    const float x0 = (float)ix, x1 = (float)iy;
    const float xx = fmaf(x0, x0, x1 * x1);

    float den = 0.f, n0 = 0.f, n1 = 0.f, n2 = 0.f;
#pragma unroll 4
    for (int j = 0; j < nc; j++) {
        float4 a = recA[j];                  // broadcast LDS
        float4 b = recB[j];
        float arg = fmaf(a.w, xx, a.z);
        arg = fmaf(a.x, x0, arg);
        arg = fmaf(a.y, x1, arg);
        float e = ex2f(arg);
        den += e;
        n0 = fmaf(e, b.x, n0);
        n1 = fmaf(e, b.y, n1);
        n2 = fmaf(e, b.z, n2);
    }
    float inv = 1.0f / den;
    g_tab[(ix << 8) + iy] = make_float4(n0 * inv, n1 * inv, n2 * inv, den);

    // -- Grid barrier (all 256 CTAs resident by occupancy construction) --
    __syncthreads();
    if (tid == 0) {
        __threadfence();
        atomicAdd(&g_arrive, 1);
        while (*(volatile unsigned*)&g_arrive < NREG) {}
        __threadfence();
    }
    __syncthreads();

    // -- Phase 2: gather this CTA's prefetched query --
    float4 vq = g_tab[(qxy.x << 8) + qxy.y];
    out[3 * qidx + 0] = vq.x;
    out[3 * qidx + 1] = vq.y;
    out[3 * qidx + 2] = vq.z;

    // -- Epilogue: last CTA resets barrier state for the next replay --
    __syncthreads();
    if (tid == 0) {
        __threadfence();
        unsigned old = atomicAdd(&g_done, 1);
        if (old == NREG - 1) {
            g_arrive = 0;
            g_done = 0;
            __threadfence();
        }
    }
}

// ---------------------------------------------------------------------------
extern "C" void kernel_launch(void* const* d_in, const int* in_sizes, int n_in,
                              void* d_out, int out_size) {
    const int*   X   = (const int*)d_in[0];     // [N,2] int32
    const int*   pat = (const int*)d_in[1];     // [P,2] int32
    const float* W2  = (const float*)d_in[2];   // [C,P] f32
    const float* sig = (const float*)d_in[3];   // [P]   f32
    float* out = (float*)d_out;
    (void)in_sizes; (void)n_in; (void)out_size;

    k_all<<<NREG, 256>>>((const int2*)X, (const int2*)pat, W2, sig, out);
}